// round 17
// baseline (speedup 1.0000x reference)
#include <cuda_runtime.h>
#include <cstdint>

constexpr int Bc = 256;   // batch
constexpr int Cc = 128;   // channels
constexpr int Hc = 1024;  // hidden
constexpr int Ic = 512;   // input features
constexpr int Oc = 128;   // output features

// Both kernels: 128x128 tile, Kstep16, 4 stages, 256 threads, 2 CTA/SM
constexpr int TW   = 128 * 20;             // A or B tile words (16 data + 4 pad)
constexpr int SW   = 2 * TW;               // stage words
constexpr int SMEMB = 4 * SW * 4;          // 81920 B

// hidden activations scratch, layout [c][b][h], values pre-rounded to tf32
__device__ float g_h[(size_t)Bc * Cc * Hc];

__device__ __forceinline__ uint32_t s2u(const void* p) {
    uint32_t a;
    asm("{ .reg .u64 t; cvta.to.shared.u64 t, %1; cvt.u32.u64 %0, t; }" : "=r"(a) : "l"(p));
    return a;
}
__device__ __forceinline__ void cp16(uint32_t dst, const float* src) {
    asm volatile("cp.async.cg.shared.global [%0], [%1], 16;" :: "r"(dst), "l"(src));
}
__device__ __forceinline__ void mma8(float4& d,
                                     uint32_t a0, uint32_t a1, uint32_t a2, uint32_t a3,
                                     uint32_t b0, uint32_t b1) {
    asm volatile(
        "mma.sync.aligned.m16n8k8.row.col.f32.tf32.tf32.f32 "
        "{%0,%1,%2,%3}, {%4,%5,%6,%7}, {%8,%9}, {%0,%1,%2,%3};"
        : "+f"(d.x), "+f"(d.y), "+f"(d.z), "+f"(d.w)
        : "r"(a0), "r"(a1), "r"(a2), "r"(a3), "r"(b0), "r"(b1));
}
// fp32 bits -> tf32 round-to-nearest (HMMA drops low 13 bits; +0x1000 = RN)
__device__ __forceinline__ uint32_t rn(uint32_t u) { return u + 0x1000u; }
#define RNID(x) (x)
#define RNRN(x) rn(x)

// compute one K16 stage, 64x32 warp tile; RNA applied to A fragments
// (B fragments always get rn)
#define COMPUTE_K16(AFP, BFP, ACC, RNA)                                         \
    _Pragma("unroll") for (int kk = 0; kk < 16; kk += 8) {                      \
        uint32_t a[4][4], b[4][2];                                              \
        _Pragma("unroll") for (int t = 0; t < 4; t++) {                         \
            a[t][0] = RNA((AFP)[(t * 16) * 20 + kk]);                           \
            a[t][1] = RNA((AFP)[(t * 16 + 8) * 20 + kk]);                       \
            a[t][2] = RNA((AFP)[(t * 16) * 20 + kk + 4]);                       \
            a[t][3] = RNA((AFP)[(t * 16 + 8) * 20 + kk + 4]);                   \
        }                                                                       \
        _Pragma("unroll") for (int u = 0; u < 4; u++) {                         \
            b[u][0] = rn((BFP)[(u * 8) * 20 + kk]);                             \
            b[u][1] = rn((BFP)[(u * 8) * 20 + kk + 4]);                         \
        }                                                                       \
        _Pragma("unroll") for (int t = 0; t < 4; t++)                           \
            _Pragma("unroll") for (int u = 0; u < 4; u++)                       \
                mma8((ACC)[t][u], a[t][0], a[t][1], a[t][2], a[t][3],           \
                     b[u][0], b[u][1]);                                         \
    }

// shared 4-stage mainloop skeleton
#define MAINLOOP(KDIM, RNA)                                                     \
    const int NIT = (KDIM) / 16;                                                \
    _Pragma("unroll")                                                           \
    for (int s = 0; s < 3; s++) {                                               \
        CPST(s);                                                                \
        asm volatile("cp.async.commit_group;" ::: "memory");                    \
    }                                                                           \
    for (int i = 0; i < NIT; i++) {                                             \
        const int sl = i & 3;                                                   \
        asm volatile("cp.async.wait_group 2;" ::: "memory");                    \
        __syncthreads();                                                        \
        if (i + 3 < NIT) CPST(i + 3);                                           \
        asm volatile("cp.async.commit_group;" ::: "memory");                    \
        const uint32_t* Afp = smw + sl * SW + faoff;                            \
        const uint32_t* Bfp = smw + sl * SW + TW + fboff;                       \
        COMPUTE_K16(Afp, Bfp, acc, RNA)                                         \
    }

#define IDX_SETUP                                                               \
    const int tid = threadIdx.x, l = tid & 31, w = tid >> 5;                    \
    const int wm = (w & 1) * 64, wn = (w >> 1) * 32;                            \
    const int lr4 = l >> 2, lc4 = l & 3;                                        \
    const int lrow = tid >> 1, lko = (tid & 1) * 8;                             \
    const int faoff = (wm + lr4) * 20 + lc4;                                    \
    const int fboff = (wn + lr4) * 20 + lc4;                                    \
    const uint32_t sbase = s2u(smw);                                            \
    const uint32_t dstA = sbase + (uint32_t)(lrow * 20 + lko) * 4;              \
    const uint32_t dstB = dstA + (uint32_t)TW * 4;                              \
    float4 acc[4][4];                                                           \
    _Pragma("unroll") for (int t = 0; t < 4; t++)                               \
        _Pragma("unroll") for (int u = 0; u < 4; u++)                           \
            acc[t][u] = make_float4(0.f, 0.f, 0.f, 0.f);

#define CPST(S)                                                                 \
    do {                                                                        \
        const uint32_t _o = (uint32_t)(((S) & 3) * SW) * 4;                     \
        cp16(dstA + _o,      srcA + (S) * 16);                                  \
        cp16(dstA + _o + 16, srcA + (S) * 16 + 4);                              \
        cp16(dstB + _o,      srcB + (S) * 16);                                  \
        cp16(dstB + _o + 16, srcB + (S) * 16 + 4);                              \
    } while (0)

// ---------------------------------------------------------------------------
// Kernel 1: h = relu(X_c @ W1_c^T + b1_c) -> g_h[c][b][h], tf32-pre-rounded
// grid (8, 2, 128), 256 threads, 2 CTA/SM
// ---------------------------------------------------------------------------
__global__ __launch_bounds__(256, 2)
void mlp_k1(const float* __restrict__ x, const float* __restrict__ w1,
            const float* __restrict__ b1) {
    extern __shared__ uint32_t smw[];
    const int c = blockIdx.z, m0 = blockIdx.y * 128, n0 = blockIdx.x * 128;
    IDX_SETUP
    const float* srcA = x  + ((size_t)(m0 + lrow) * Cc + c) * Ic + lko;
    const float* srcB = w1 + ((size_t)c * Hc + n0 + lrow) * Ic + lko;

    MAINLOOP(Ic, RNRN)

    #pragma unroll
    for (int t = 0; t < 4; t++) {
        const int r0 = m0 + wm + t * 16 + lr4;
        #pragma unroll
        for (int u = 0; u < 4; u++) {
            const int n = n0 + wn + u * 8 + lc4 * 2;
            const float2 bb = *(const float2*)&b1[c * Hc + n];
            // relu then pre-round to tf32 (bits+0x1000): k2's HMMA truncation
            // yields exactly RN(v) — numerics identical to rn() at load time.
            float vx = fmaxf(acc[t][u].x + bb.x, 0.f);
            float vy = fmaxf(acc[t][u].y + bb.y, 0.f);
            float vz = fmaxf(acc[t][u].z + bb.x, 0.f);
            float vw = fmaxf(acc[t][u].w + bb.y, 0.f);
            float2 lo = {__uint_as_float(__float_as_uint(vx) + 0x1000u),
                         __uint_as_float(__float_as_uint(vy) + 0x1000u)};
            float2 hi = {__uint_as_float(__float_as_uint(vz) + 0x1000u),
                         __uint_as_float(__float_as_uint(vw) + 0x1000u)};
            *(float2*)&g_h[((size_t)c * Bc + r0) * Hc + n]     = lo;
            *(float2*)&g_h[((size_t)c * Bc + r0 + 8) * Hc + n] = hi;
        }
    }
}

// ---------------------------------------------------------------------------
// Kernel 2: out[b, :, c] = h[c, b, :] @ W2_c^T + b2_c   (output (B, O, C))
// grid (1, 2, 128) = 256 CTAs, 256 threads, 2 CTA/SM -> fully co-resident
// A fragments pre-rounded in g_h -> no rn() on A side.
// ---------------------------------------------------------------------------
__global__ __launch_bounds__(256, 2)
void mlp_k2(const float* __restrict__ w2, const float* __restrict__ b2,
            float* __restrict__ out) {
    extern __shared__ uint32_t smw[];
    const int c = blockIdx.z, m0 = blockIdx.y * 128;
    IDX_SETUP
    const float* srcA = g_h + ((size_t)c * Bc + m0 + lrow) * Hc + lko;
    const float* srcB = w2  + ((size_t)c * Oc + lrow) * Hc + lko;

    MAINLOOP(Hc, RNID)

    #pragma unroll
    for (int t = 0; t < 4; t++) {
        const int r0 = m0 + wm + t * 16 + lr4;
        #pragma unroll
        for (int u = 0; u < 4; u++) {
            const int n = wn + u * 8 + lc4 * 2;
            const float2 bb = *(const float2*)&b2[c * Oc + n];
            out[((size_t)r0 * Oc + n) * Cc + c]           = acc[t][u].x + bb.x;
            out[((size_t)r0 * Oc + n + 1) * Cc + c]       = acc[t][u].y + bb.y;
            out[((size_t)(r0 + 8) * Oc + n) * Cc + c]     = acc[t][u].z + bb.x;
            out[((size_t)(r0 + 8) * Oc + n + 1) * Cc + c] = acc[t][u].w + bb.y;
        }
    }
}

extern "C" void kernel_launch(void* const* d_in, const int* in_sizes, int n_in,
                              void* d_out, int out_size) {
    const float* x  = (const float*)d_in[0];
    const float* w1 = (const float*)d_in[1];
    const float* b1 = (const float*)d_in[2];
    const float* w2 = (const float*)d_in[3];
    const float* b2 = (const float*)d_in[4];
    float* out = (float*)d_out;

    static bool attr_set = false;
    if (!attr_set) {
        cudaFuncSetAttribute(mlp_k1, cudaFuncAttributeMaxDynamicSharedMemorySize, SMEMB);
        cudaFuncSetAttribute(mlp_k2, cudaFuncAttributeMaxDynamicSharedMemorySize, SMEMB);
        attr_set = true;
    }

    dim3 grid1(Hc / 128, Bc / 128, Cc);   // (8, 2, 128) = 2048 CTAs
    dim3 grid2(1,        Bc / 128, Cc);   // (1, 2, 128) = 256 CTAs, co-resident
    mlp_k1<<<grid1, dim3(256), SMEMB>>>(x, w1, b1);
    mlp_k2<<<grid2, dim3(256), SMEMB>>>(w2, b2, out);
}